// round 11
// baseline (speedup 1.0000x reference)
#include <cuda_runtime.h>
#include <cstdint>
#include <math.h>

#define BATCH 4
#define CIN   256
#define CKEY  448
#define NPIX  4096

typedef unsigned long long u64;

__device__ __forceinline__ u64 pack2(float lo, float hi) {
    u64 r; asm("mov.b64 %0,{%1,%2};" : "=l"(r) : "f"(lo), "f"(hi)); return r;
}
__device__ __forceinline__ void unpack2(u64 v, float& lo, float& hi) {
    asm("mov.b64 {%0,%1},%2;" : "=f"(lo), "=f"(hi) : "l"(v));
}
__device__ __forceinline__ void fma2(u64& d, u64 a, u64 b) {
    asm("fma.rn.f32x2 %0,%1,%2,%0;" : "+l"(d) : "l"(a), "l"(b));
}
__device__ __forceinline__ u64 mul2(u64 a, u64 b) {
    u64 r; asm("mul.rn.f32x2 %0,%1,%2;" : "=l"(r) : "l"(a), "l"(b)); return r;
}

__device__ float g_Fq[(size_t)BATCH * NPIX * CKEY];   // [b][n][ck]
__device__ float g_G [(size_t)BATCH * CKEY * NPIX];   // [b][ck][m]
__device__ float g_Hv[(size_t)BATCH * NPIX * CIN];    // [b][m][c]
__device__ float g_sM[BATCH * CIN];
__device__ float g_sR[BATCH * CIN];

// ---------------- projection: out = W @ X + b ----------------
__global__ __launch_bounds__(256) void proj_kernel(
    const float* __restrict__ X, const float* __restrict__ W,
    const float* __restrict__ bias, float* __restrict__ out,
    int inC, int outC, int transOut)
{
    __shared__ float Xs[128 * 20];
    __shared__ float Ws[64 * 20];
    const int n0 = blockIdx.x * 128, o0 = blockIdx.y * 64, b = blockIdx.z;
    const int tid = threadIdx.x, ty = tid >> 4, tx = tid & 15;
    const float* Xb = X + (size_t)b * inC * NPIX;

    float acc[8][4];
    #pragma unroll
    for (int i = 0; i < 8; i++)
        #pragma unroll
        for (int j = 0; j < 4; j++) acc[i][j] = 0.f;

    for (int c0 = 0; c0 < inC; c0 += 16) {
        __syncthreads();
        #pragma unroll
        for (int p = 0; p < 8; p++) {
            int idx = tid + p * 256;
            int nn = idx & 127, cc = idx >> 7;
            Xs[nn * 20 + cc] = Xb[(size_t)(c0 + cc) * NPIX + n0 + nn];
        }
        #pragma unroll
        for (int p = 0; p < 4; p++) {
            int idx = tid + p * 256;
            int cc = idx & 15, oo = idx >> 4;
            Ws[oo * 20 + cc] = W[(size_t)(o0 + oo) * inC + c0 + cc];
        }
        __syncthreads();
        #pragma unroll
        for (int cg = 0; cg < 4; cg++) {
            float4 bv[4];
            #pragma unroll
            for (int j = 0; j < 4; j++)
                bv[j] = *(const float4*)&Ws[(tx + 16 * j) * 20 + cg * 4];
            #pragma unroll
            for (int i = 0; i < 8; i++) {
                float4 av = *(const float4*)&Xs[(ty * 8 + i) * 20 + cg * 4];
                #pragma unroll
                for (int j = 0; j < 4; j++) {
                    acc[i][j] = fmaf(av.x, bv[j].x, acc[i][j]);
                    acc[i][j] = fmaf(av.y, bv[j].y, acc[i][j]);
                    acc[i][j] = fmaf(av.z, bv[j].z, acc[i][j]);
                    acc[i][j] = fmaf(av.w, bv[j].w, acc[i][j]);
                }
            }
        }
    }
    #pragma unroll
    for (int j = 0; j < 4; j++) {
        int o = o0 + tx + 16 * j;
        float bb = bias[o];
        #pragma unroll
        for (int i = 0; i < 8; i++) {
            int n = n0 + ty * 8 + i;
            float v = acc[i][j] + bb;
            if (transOut) out[((size_t)b * outC + o) * NPIX + n] = v;
            else          out[((size_t)b * NPIX + n) * outC + o] = v;
        }
    }
}

// ---------------- MVN stats per (b,c) ----------------
__global__ void mvn_stats_kernel(const float* __restrict__ x)
{
    const int bc = blockIdx.x;
    const float* p = x + (size_t)bc * NPIX;
    float s = 0.f, ss = 0.f;
    for (int i = threadIdx.x; i < NPIX; i += 256) {
        float v = p[i];
        s += v; ss = fmaf(v, v, ss);
    }
    #pragma unroll
    for (int o = 16; o > 0; o >>= 1) {
        s  += __shfl_xor_sync(0xffffffffu, s,  o);
        ss += __shfl_xor_sync(0xffffffffu, ss, o);
    }
    __shared__ float shs[8], shss[8];
    int w = threadIdx.x >> 5, l = threadIdx.x & 31;
    if (l == 0) { shs[w] = s; shss[w] = ss; }
    __syncthreads();
    if (threadIdx.x == 0) {
        float S = 0.f, SS = 0.f;
        #pragma unroll
        for (int i = 0; i < 8; i++) { S += shs[i]; SS += shss[i]; }
        float mean = S / (float)NPIX;
        float var  = (SS - S * mean) / (float)(NPIX - 1);
        g_sM[bc] = mean;
        g_sR[bc] = rsqrtf(var + 1e-5f);
    }
}

// ---------------- fused attention + epilogue (f32x2 packed) ----------------
#define FQ_LD  452
#define BUF_LD 68
#define HV_LD  260
#define PS_LD  68
#define ATTN_SMEM_BYTES ((32 * FQ_LD + 64 * BUF_LD + 32 * PS_LD + 64) * 4)

__global__ __launch_bounds__(256, 2) void attn_kernel(
    const float* __restrict__ Fqg, const float* __restrict__ Gg,
    const float* __restrict__ Hvg,
    const float* __restrict__ content,
    const int*   __restrict__ cmask,
    const int*   __restrict__ smask,
    float* __restrict__ out)
{
    extern __shared__ float sm[];
    float* Fqs = sm;                     // [32][452]
    float* buf = Fqs + 32 * FQ_LD;       // G chunk [64c][64m] or Hv chunk [16k][256c]
    float* Ps  = buf + 64 * BUF_LD;      // [32][68]
    float* smi = Ps + 32 * PS_LD;        // [64]

    const int b = blockIdx.y, n0 = blockIdx.x * 32;
    const int tid = threadIdx.x, ty = tid >> 4, tx = tid & 15;
    const int r0 = 2 * ty, r1 = r0 + 1;

    const float* Fqb = Fqg + ((size_t)b * NPIX + n0) * CKEY;
    const float* Gb  = Gg  + (size_t)b * CKEY * NPIX;
    const float* Hb  = Hvg + (size_t)b * NPIX * CIN;

    #pragma unroll
    for (int p = 0; p < 14; p++) {
        int idx4 = tid + p * 256;
        int cc4 = idx4 % 112, nn = idx4 / 112;
        *(float4*)&Fqs[nn * FQ_LD + cc4 * 4] = *(const float4*)&Fqb[(size_t)nn * CKEY + cc4 * 4];
    }
    const bool rm0 = cmask[b * NPIX + n0 + r0] != 0;
    const bool rm1 = cmask[b * NPIX + n0 + r1] != 0;

    // packed accumulators: aM/aV[row][g*2+h] holds channels (g*64+tx*4+2h, +1)
    u64 aM[2][8], aV[2][8];
    #pragma unroll
    for (int i = 0; i < 2; i++)
        #pragma unroll
        for (int c = 0; c < 8; c++) { aM[i][c] = 0ULL; aV[i][c] = 0ULL; }
    float accD0 = 0.f, accD1 = 0.f;

    for (int m0 = 0; m0 < NPIX; m0 += 64) {
        if (tid < 64) smi[tid] = (smask[b * NPIX + m0 + tid] == 0) ? 1.f : 0.f;

        // s pairs: (j0,j1) and (j2,j3) for each of the two query rows
        u64 s0p0 = 0ULL, s0p1 = 0ULL, s1p0 = 0ULL, s1p1 = 0ULL;

        // Phase A: S = Fq . G  (packed over key pairs)
        for (int ch = 0; ch < 7; ch++) {
            const int c0 = ch * 64;
            __syncthreads();
            #pragma unroll
            for (int p = 0; p < 4; p++) {
                int idx4 = tid + p * 256;
                int mm4 = idx4 & 15, cc = idx4 >> 4;
                *(float4*)&buf[cc * BUF_LD + mm4 * 4] =
                    *(const float4*)&Gb[(size_t)(c0 + cc) * NPIX + m0 + mm4 * 4];
            }
            __syncthreads();
            #pragma unroll 4
            for (int cs = 0; cs < 16; cs++) {
                int cc = cs * 4;
                float4 a0v = *(const float4*)&Fqs[r0 * FQ_LD + c0 + cc];
                float4 a1v = *(const float4*)&Fqs[r1 * FQ_LD + c0 + cc];
                const float* a0 = &a0v.x;
                const float* a1 = &a1v.x;
                #pragma unroll
                for (int q = 0; q < 4; q++) {
                    ulonglong2 bq = *(const ulonglong2*)&buf[(cc + q) * BUF_LD + tx * 4];
                    u64 a0d = pack2(a0[q], a0[q]);
                    u64 a1d = pack2(a1[q], a1[q]);
                    fma2(s0p0, a0d, bq.x); fma2(s0p1, a0d, bq.y);
                    fma2(s1p0, a1d, bq.x); fma2(s1p1, a1d, bq.y);
                }
            }
        }

        // Phase B: P = exp(S), masked -> 0 (matches softmax of -1e15 exactly)
        float s0[4], s1[4];
        unpack2(s0p0, s0[0], s0[1]); unpack2(s0p1, s0[2], s0[3]);
        unpack2(s1p0, s1[0], s1[1]); unpack2(s1p1, s1[2], s1[3]);
        #pragma unroll
        for (int j = 0; j < 4; j++) {
            float msk = smi[tx * 4 + j];
            float e0 = __expf(s0[j]); if (rm0 && msk > 0.5f) e0 = 0.f;
            float e1 = __expf(s1[j]); if (rm1 && msk > 0.5f) e1 = 0.f;
            Ps[r0 * PS_LD + tx * 4 + j] = e0;
            Ps[r1 * PS_LD + tx * 4 + j] = e1;
            accD0 += e0; accD1 += e1;
        }

        // Phase C: accumulate P.Hv and P.Hv^2 (packed over channel pairs)
        for (int kc = 0; kc < 4; kc++) {
            __syncthreads();
            #pragma unroll
            for (int p = 0; p < 4; p++) {
                int idx4 = tid + p * 256;
                int c4 = idx4 & 63, kk = idx4 >> 6;
                *(float4*)&buf[kk * HV_LD + c4 * 4] =
                    *(const float4*)&Hb[(size_t)(m0 + kc * 16 + kk) * CIN + c4 * 4];
            }
            __syncthreads();
            for (int kk = 0; kk < 16; kk++) {
                float w0 = Ps[r0 * PS_LD + kc * 16 + kk];
                float w1 = Ps[r1 * PS_LD + kc * 16 + kk];
                u64 w0p = pack2(w0, w0);
                u64 w1p = pack2(w1, w1);
                #pragma unroll
                for (int g = 0; g < 4; g++) {
                    ulonglong2 v = *(const ulonglong2*)&buf[kk * HV_LD + g * 64 + tx * 4];
                    u64 sx = mul2(v.x, v.x);
                    u64 sy = mul2(v.y, v.y);
                    fma2(aM[0][g*2],   w0p, v.x); fma2(aM[0][g*2+1], w0p, v.y);
                    fma2(aV[0][g*2],   w0p, sx ); fma2(aV[0][g*2+1], w0p, sy );
                    fma2(aM[1][g*2],   w1p, v.x); fma2(aM[1][g*2+1], w1p, v.y);
                    fma2(aV[1][g*2],   w1p, sx ); fma2(aV[1][g*2+1], w1p, sy );
                }
            }
        }
    }

    // denominator: reduce across the 16 tx lanes sharing a row
    #pragma unroll
    for (int o = 1; o < 16; o <<= 1) {
        accD0 += __shfl_xor_sync(0xffffffffu, accD0, o);
        accD1 += __shfl_xor_sync(0xffffffffu, accD1, o);
    }
    float invD[2] = {1.f / accD0, 1.f / accD1};

    const float* Cb = content + (size_t)b * CIN * NPIX;
    float* Ob = out + (size_t)b * CIN * NPIX;
    #pragma unroll
    for (int i = 0; i < 2; i++) {
        int n = n0 + r0 + i;
        #pragma unroll
        for (int g = 0; g < 4; g++) {
            #pragma unroll
            for (int h = 0; h < 2; h++) {
                float m0v, m1v, v0v, v1v;
                unpack2(aM[i][g*2+h], m0v, m1v);
                unpack2(aV[i][g*2+h], v0v, v1v);
                #pragma unroll
                for (int e = 0; e < 2; e++) {
                    int c = g * 64 + tx * 4 + 2 * h + e;
                    float mean = (e ? m1v : m0v) * invD[i];
                    float m2   = (e ? v1v : v0v) * invD[i];
                    float sd = sqrtf(fmaxf(m2 - mean * mean, 0.f));
                    float x = Cb[(size_t)c * NPIX + n];
                    float nz = (x - g_sM[b * CIN + c]) * g_sR[b * CIN + c];
                    Ob[(size_t)c * NPIX + n] = fmaf(sd, nz, mean);
                }
            }
        }
    }
}

extern "C" void kernel_launch(void* const* d_in, const int* in_sizes, int n_in,
                              void* d_out, int out_size) {
    const float* content  = (const float*)d_in[0];
    const float* style    = (const float*)d_in[1];
    const float* ckey     = (const float*)d_in[2];
    const float* skey     = (const float*)d_in[3];
    const int*   cmask    = (const int*)d_in[4];
    const int*   smask    = (const int*)d_in[5];
    const float* Wf = (const float*)d_in[6];
    const float* bf = (const float*)d_in[7];
    const float* Wg = (const float*)d_in[8];
    const float* bg = (const float*)d_in[9];
    const float* Wh = (const float*)d_in[10];
    const float* bh = (const float*)d_in[11];
    float* out = (float*)d_out;

    float *Fq, *G, *Hv;
    cudaGetSymbolAddress((void**)&Fq, g_Fq);
    cudaGetSymbolAddress((void**)&G,  g_G);
    cudaGetSymbolAddress((void**)&Hv, g_Hv);
    cudaFuncSetAttribute(attn_kernel, cudaFuncAttributeMaxDynamicSharedMemorySize,
                         ATTN_SMEM_BYTES);

    proj_kernel<<<dim3(32, 7, BATCH), 256>>>(ckey, Wf, bf, Fq, CKEY, CKEY, 0);
    proj_kernel<<<dim3(32, 7, BATCH), 256>>>(skey, Wg, bg, G,  CKEY, CKEY, 1);
    proj_kernel<<<dim3(32, 4, BATCH), 256>>>(style, Wh, bh, Hv, CIN, CIN, 0);
    mvn_stats_kernel<<<BATCH * CIN, 256>>>(content);
    attn_kernel<<<dim3(NPIX / 32, BATCH), 256, ATTN_SMEM_BYTES>>>(
        Fq, G, Hv, content, cmask, smask, out);
}

// round 12
// speedup vs baseline: 1.0084x; 1.0084x over previous
#include <cuda_runtime.h>
#include <cstdint>
#include <math.h>

#define BATCH 4
#define CIN   256
#define CKEY  448
#define NPIX  4096

typedef unsigned long long u64;

__device__ __forceinline__ u64 pack2(float lo, float hi) {
    u64 r; asm("mov.b64 %0,{%1,%2};" : "=l"(r) : "f"(lo), "f"(hi)); return r;
}
__device__ __forceinline__ void unpack2(u64 v, float& lo, float& hi) {
    asm("mov.b64 {%0,%1},%2;" : "=f"(lo), "=f"(hi) : "l"(v));
}
__device__ __forceinline__ void fma2(u64& d, u64 a, u64 b) {
    asm("fma.rn.f32x2 %0,%1,%2,%0;" : "+l"(d) : "l"(a), "l"(b));
}
__device__ __forceinline__ u64 mul2(u64 a, u64 b) {
    u64 r; asm("mul.rn.f32x2 %0,%1,%2;" : "=l"(r) : "l"(a), "l"(b)); return r;
}
__device__ __forceinline__ uint32_t smem_u32(const void* p) {
    uint32_t a;
    asm("{ .reg .u64 t; cvta.to.shared.u64 t, %1; cvt.u32.u64 %0, t; }" : "=r"(a) : "l"(p));
    return a;
}
__device__ __forceinline__ void cpasync16(uint32_t dst, const void* src) {
    asm volatile("cp.async.cg.shared.global [%0], [%1], 16;" :: "r"(dst), "l"(src));
}
#define CP_COMMIT() asm volatile("cp.async.commit_group;")
#define CP_WAIT0()  asm volatile("cp.async.wait_group 0;")

__device__ float g_Fq[(size_t)BATCH * NPIX * CKEY];   // [b][n][ck]
__device__ float g_G [(size_t)BATCH * CKEY * NPIX];   // [b][ck][m]
__device__ float g_Hv[(size_t)BATCH * NPIX * CIN];    // [b][m][c]
__device__ float g_sM[BATCH * CIN];
__device__ float g_sR[BATCH * CIN];

// ---------------- projection: out = W @ X + b ----------------
__global__ __launch_bounds__(256) void proj_kernel(
    const float* __restrict__ X, const float* __restrict__ W,
    const float* __restrict__ bias, float* __restrict__ out,
    int inC, int outC, int transOut)
{
    __shared__ float Xs[128 * 20];
    __shared__ float Ws[64 * 20];
    const int n0 = blockIdx.x * 128, o0 = blockIdx.y * 64, b = blockIdx.z;
    const int tid = threadIdx.x, ty = tid >> 4, tx = tid & 15;
    const float* Xb = X + (size_t)b * inC * NPIX;

    float acc[8][4];
    #pragma unroll
    for (int i = 0; i < 8; i++)
        #pragma unroll
        for (int j = 0; j < 4; j++) acc[i][j] = 0.f;

    for (int c0 = 0; c0 < inC; c0 += 16) {
        __syncthreads();
        #pragma unroll
        for (int p = 0; p < 8; p++) {
            int idx = tid + p * 256;
            int nn = idx & 127, cc = idx >> 7;
            Xs[nn * 20 + cc] = Xb[(size_t)(c0 + cc) * NPIX + n0 + nn];
        }
        #pragma unroll
        for (int p = 0; p < 4; p++) {
            int idx = tid + p * 256;
            int cc = idx & 15, oo = idx >> 4;
            Ws[oo * 20 + cc] = W[(size_t)(o0 + oo) * inC + c0 + cc];
        }
        __syncthreads();
        #pragma unroll
        for (int cg = 0; cg < 4; cg++) {
            float4 bv[4];
            #pragma unroll
            for (int j = 0; j < 4; j++)
                bv[j] = *(const float4*)&Ws[(tx + 16 * j) * 20 + cg * 4];
            #pragma unroll
            for (int i = 0; i < 8; i++) {
                float4 av = *(const float4*)&Xs[(ty * 8 + i) * 20 + cg * 4];
                #pragma unroll
                for (int j = 0; j < 4; j++) {
                    acc[i][j] = fmaf(av.x, bv[j].x, acc[i][j]);
                    acc[i][j] = fmaf(av.y, bv[j].y, acc[i][j]);
                    acc[i][j] = fmaf(av.z, bv[j].z, acc[i][j]);
                    acc[i][j] = fmaf(av.w, bv[j].w, acc[i][j]);
                }
            }
        }
    }
    #pragma unroll
    for (int j = 0; j < 4; j++) {
        int o = o0 + tx + 16 * j;
        float bb = bias[o];
        #pragma unroll
        for (int i = 0; i < 8; i++) {
            int n = n0 + ty * 8 + i;
            float v = acc[i][j] + bb;
            if (transOut) out[((size_t)b * outC + o) * NPIX + n] = v;
            else          out[((size_t)b * NPIX + n) * outC + o] = v;
        }
    }
}

// ---------------- MVN stats per (b,c) ----------------
__global__ void mvn_stats_kernel(const float* __restrict__ x)
{
    const int bc = blockIdx.x;
    const float* p = x + (size_t)bc * NPIX;
    float s = 0.f, ss = 0.f;
    for (int i = threadIdx.x; i < NPIX; i += 256) {
        float v = p[i];
        s += v; ss = fmaf(v, v, ss);
    }
    #pragma unroll
    for (int o = 16; o > 0; o >>= 1) {
        s  += __shfl_xor_sync(0xffffffffu, s,  o);
        ss += __shfl_xor_sync(0xffffffffu, ss, o);
    }
    __shared__ float shs[8], shss[8];
    int w = threadIdx.x >> 5, l = threadIdx.x & 31;
    if (l == 0) { shs[w] = s; shss[w] = ss; }
    __syncthreads();
    if (threadIdx.x == 0) {
        float S = 0.f, SS = 0.f;
        #pragma unroll
        for (int i = 0; i < 8; i++) { S += shs[i]; SS += shss[i]; }
        float mean = S / (float)NPIX;
        float var  = (SS - S * mean) / (float)(NPIX - 1);
        g_sM[bc] = mean;
        g_sR[bc] = rsqrtf(var + 1e-5f);
    }
}

// ---------------- fused attention + epilogue (f32x2 + cp.async pipeline) -----
#define FQ_LD  452
#define BUF_LD 68
#define HV_LD  260
#define PS_LD  68
#define CHUNK_FLOATS 4352                       // max(64*68, 16*260)
#define ATTN_SMEM_BYTES ((32 * FQ_LD + 2 * CHUNK_FLOATS + 32 * PS_LD + 64) * 4)

__device__ __forceinline__ void load_G_chunk(uint32_t bufa, const float* Gb,
                                             int m0, int ch, int tid) {
    const int c0 = ch * 64;
    #pragma unroll
    for (int p = 0; p < 4; p++) {
        int idx4 = tid + p * 256;
        int mm4 = idx4 & 15, cc = idx4 >> 4;
        cpasync16(bufa + (uint32_t)(cc * BUF_LD + mm4 * 4) * 4u,
                  Gb + (size_t)(c0 + cc) * NPIX + m0 + mm4 * 4);
    }
}
__device__ __forceinline__ void load_H_chunk(uint32_t bufa, const float* Hb,
                                             int m0, int kc, int tid) {
    #pragma unroll
    for (int p = 0; p < 4; p++) {
        int idx4 = tid + p * 256;
        int c4 = idx4 & 63, kk = idx4 >> 6;
        cpasync16(bufa + (uint32_t)(kk * HV_LD + c4 * 4) * 4u,
                  Hb + (size_t)(m0 + kc * 16 + kk) * CIN + c4 * 4);
    }
}

__global__ __launch_bounds__(256, 2) void attn_kernel(
    const float* __restrict__ Fqg, const float* __restrict__ Gg,
    const float* __restrict__ Hvg,
    const float* __restrict__ content,
    const int*   __restrict__ cmask,
    const int*   __restrict__ smask,
    float* __restrict__ out)
{
    extern __shared__ float sm[];
    float* Fqs  = sm;                          // [32][452]
    float* bufA = Fqs + 32 * FQ_LD;            // chunk buffer 0
    float* bufB = bufA + CHUNK_FLOATS;         // chunk buffer 1
    float* Ps   = bufB + CHUNK_FLOATS;         // [32][68]
    float* smi  = Ps + 32 * PS_LD;             // [64]

    const int b = blockIdx.y, n0 = blockIdx.x * 32;
    const int tid = threadIdx.x, ty = tid >> 4, tx = tid & 15;
    const int r0 = 2 * ty, r1 = r0 + 1;

    const float* Fqb = Fqg + ((size_t)b * NPIX + n0) * CKEY;
    const float* Gb  = Gg  + (size_t)b * CKEY * NPIX;
    const float* Hb  = Hvg + (size_t)b * NPIX * CIN;

    float* bufp[2]  = {bufA, bufB};
    uint32_t bufu[2] = {smem_u32(bufA), smem_u32(bufB)};
    int par = 0;

    // stage Fq block [32 x 448] + first G chunk, one barrier
    #pragma unroll
    for (int p = 0; p < 14; p++) {
        int idx4 = tid + p * 256;
        int cc4 = idx4 % 112, nn = idx4 / 112;
        *(float4*)&Fqs[nn * FQ_LD + cc4 * 4] = *(const float4*)&Fqb[(size_t)nn * CKEY + cc4 * 4];
    }
    load_G_chunk(bufu[0], Gb, 0, 0, tid);
    CP_COMMIT(); CP_WAIT0();
    const bool rm0 = cmask[b * NPIX + n0 + r0] != 0;
    const bool rm1 = cmask[b * NPIX + n0 + r1] != 0;
    __syncthreads();

    u64 aM[2][8], aV[2][8];
    #pragma unroll
    for (int i = 0; i < 2; i++)
        #pragma unroll
        for (int c = 0; c < 8; c++) { aM[i][c] = 0ULL; aV[i][c] = 0ULL; }
    float accD0 = 0.f, accD1 = 0.f;

    for (int m0 = 0; m0 < NPIX; m0 += 64) {
        if (tid < 64) smi[tid] = (smask[b * NPIX + m0 + tid] == 0) ? 1.f : 0.f;

        u64 s0p0 = 0ULL, s0p1 = 0ULL, s1p0 = 0ULL, s1p1 = 0ULL;

        // ---- Phase A: S = Fq . G  (pipelined chunks) ----
        for (int ch = 0; ch < 7; ch++) {
            if (ch < 6) load_G_chunk(bufu[par ^ 1], Gb, m0, ch + 1, tid);
            else        load_H_chunk(bufu[par ^ 1], Hb, m0, 0, tid);
            CP_COMMIT();

            const float* buf = bufp[par];
            const int c0 = ch * 64;
            #pragma unroll 4
            for (int cs = 0; cs < 16; cs++) {
                int cc = cs * 4;
                float4 a0v = *(const float4*)&Fqs[r0 * FQ_LD + c0 + cc];
                float4 a1v = *(const float4*)&Fqs[r1 * FQ_LD + c0 + cc];
                const float* a0 = &a0v.x;
                const float* a1 = &a1v.x;
                #pragma unroll
                for (int q = 0; q < 4; q++) {
                    ulonglong2 bq = *(const ulonglong2*)&buf[(cc + q) * BUF_LD + tx * 4];
                    u64 a0d = pack2(a0[q], a0[q]);
                    u64 a1d = pack2(a1[q], a1[q]);
                    fma2(s0p0, a0d, bq.x); fma2(s0p1, a0d, bq.y);
                    fma2(s1p0, a1d, bq.x); fma2(s1p1, a1d, bq.y);
                }
            }
            CP_WAIT0(); __syncthreads(); par ^= 1;
        }

        // ---- Phase B: P = exp(S), masked -> 0 ----
        float s0[4], s1[4];
        unpack2(s0p0, s0[0], s0[1]); unpack2(s0p1, s0[2], s0[3]);
        unpack2(s1p0, s1[0], s1[1]); unpack2(s1p1, s1[2], s1[3]);
        #pragma unroll
        for (int j = 0; j < 4; j++) {
            float msk = smi[tx * 4 + j];
            float e0 = __expf(s0[j]); if (rm0 && msk > 0.5f) e0 = 0.f;
            float e1 = __expf(s1[j]); if (rm1 && msk > 0.5f) e1 = 0.f;
            Ps[r0 * PS_LD + tx * 4 + j] = e0;
            Ps[r1 * PS_LD + tx * 4 + j] = e1;
            accD0 += e0; accD1 += e1;
        }
        __syncwarp();   // Ps rows are produced & consumed within one warp

        // ---- Phase C: accumulate P.Hv, P.Hv^2 (pipelined chunks) ----
        for (int kc = 0; kc < 4; kc++) {
            if (kc < 3) load_H_chunk(bufu[par ^ 1], Hb, m0, kc + 1, tid);
            else        load_G_chunk(bufu[par ^ 1], Gb, (m0 + 64) & (NPIX - 1), 0, tid);
            CP_COMMIT();

            const float* buf = bufp[par];
            for (int kk = 0; kk < 16; kk++) {
                float w0 = Ps[r0 * PS_LD + kc * 16 + kk];
                float w1 = Ps[r1 * PS_LD + kc * 16 + kk];
                u64 w0p = pack2(w0, w0);
                u64 w1p = pack2(w1, w1);
                #pragma unroll
                for (int g = 0; g < 4; g++) {
                    ulonglong2 v = *(const ulonglong2*)&buf[kk * HV_LD + g * 64 + tx * 4];
                    u64 sx = mul2(v.x, v.x);
                    u64 sy = mul2(v.y, v.y);
                    fma2(aM[0][g*2],   w0p, v.x); fma2(aM[0][g*2+1], w0p, v.y);
                    fma2(aV[0][g*2],   w0p, sx ); fma2(aV[0][g*2+1], w0p, sy );
                    fma2(aM[1][g*2],   w1p, v.x); fma2(aM[1][g*2+1], w1p, v.y);
                    fma2(aV[1][g*2],   w1p, sx ); fma2(aV[1][g*2+1], w1p, sy );
                }
            }
            CP_WAIT0(); __syncthreads(); par ^= 1;
        }
    }

    // denominator: reduce across the 16 tx lanes sharing a row
    #pragma unroll
    for (int o = 1; o < 16; o <<= 1) {
        accD0 += __shfl_xor_sync(0xffffffffu, accD0, o);
        accD1 += __shfl_xor_sync(0xffffffffu, accD1, o);
    }
    float invD[2] = {1.f / accD0, 1.f / accD1};

    const float* Cb = content + (size_t)b * CIN * NPIX;
    float* Ob = out + (size_t)b * CIN * NPIX;
    #pragma unroll
    for (int i = 0; i < 2; i++) {
        int n = n0 + r0 + i;
        #pragma unroll
        for (int g = 0; g < 4; g++) {
            #pragma unroll
            for (int h = 0; h < 2; h++) {
                float m0v, m1v, v0v, v1v;
                unpack2(aM[i][g*2+h], m0v, m1v);
                unpack2(aV[i][g*2+h], v0v, v1v);
                #pragma unroll
                for (int e = 0; e < 2; e++) {
                    int c = g * 64 + tx * 4 + 2 * h + e;
                    float mean = (e ? m1v : m0v) * invD[i];
                    float m2   = (e ? v1v : v0v) * invD[i];
                    float sd = sqrtf(fmaxf(m2 - mean * mean, 0.f));
                    float x = Cb[(size_t)c * NPIX + n];
                    float nz = (x - g_sM[b * CIN + c]) * g_sR[b * CIN + c];
                    Ob[(size_t)c * NPIX + n] = fmaf(sd, nz, mean);
                }
            }
        }
    }
}

extern "C" void kernel_launch(void* const* d_in, const int* in_sizes, int n_in,
                              void* d_out, int out_size) {
    const float* content  = (const float*)d_in[0];
    const float* style    = (const float*)d_in[1];
    const float* ckey     = (const float*)d_in[2];
    const float* skey     = (const float*)d_in[3];
    const int*   cmask    = (const int*)d_in[4];
    const int*   smask    = (const int*)d_in[5];
    const float* Wf = (const float*)d_in[6];
    const float* bf = (const float*)d_in[7];
    const float* Wg = (const float*)d_in[8];
    const float* bg = (const float*)d_in[9];
    const float* Wh = (const float*)d_in[10];
    const float* bh = (const float*)d_in[11];
    float* out = (float*)d_out;

    float *Fq, *G, *Hv;
    cudaGetSymbolAddress((void**)&Fq, g_Fq);
    cudaGetSymbolAddress((void**)&G,  g_G);
    cudaGetSymbolAddress((void**)&Hv, g_Hv);
    cudaFuncSetAttribute(attn_kernel, cudaFuncAttributeMaxDynamicSharedMemorySize,
                         ATTN_SMEM_BYTES);

    proj_kernel<<<dim3(32, 7, BATCH), 256>>>(ckey, Wf, bf, Fq, CKEY, CKEY, 0);
    proj_kernel<<<dim3(32, 7, BATCH), 256>>>(skey, Wg, bg, G,  CKEY, CKEY, 1);
    proj_kernel<<<dim3(32, 4, BATCH), 256>>>(style, Wh, bh, Hv, CIN, CIN, 0);
    mvn_stats_kernel<<<BATCH * CIN, 256>>>(content);
    attn_kernel<<<dim3(NPIX / 32, BATCH), 256, ATTN_SMEM_BYTES>>>(
        Fq, G, Hv, content, cmask, smask, out);
}